// round 10
// baseline (speedup 1.0000x reference)
#include <cuda_runtime.h>
#include <cuda_fp16.h>
#include <cstdint>
#include <cstddef>

// ---------------------------------------------------------------------------
// Problem constants
// ---------------------------------------------------------------------------
#define N_TOK   8192
#define DIN     4096
#define DOUT    4096
#define S_RANK  256
#define S_CAT   512

#define BM      128
#define BN      128
#define BK      64          // 64 fp16 = 128B row -> SW128 swizzle
#define STAGES  3
#define THREADS 256

#define TILE_BYTES (128 * 128)                       // 16KB per fp16 tile stage
#define G_SMEM     (STAGES * 2 * TILE_BYTES)         // 98304 -> 2 CTAs/SM

// ---------------------------------------------------------------------------
// Scratch (device globals; no runtime allocation). No g_xh.
// ---------------------------------------------------------------------------
__device__ __half g_B1[(size_t)S_CAT * DIN];     // sign(V)*v2*v1*u2   4 MB
__device__ __half g_B2[(size_t)DOUT * S_CAT];    // sign(U)*u1         4 MB
__device__ __half g_H [(size_t)N_TOK * S_CAT];   // H fp16             8 MB

// ---------------------------------------------------------------------------
// Helpers
// ---------------------------------------------------------------------------
__device__ __forceinline__ uint32_t smem_u32(const void* p) {
    uint32_t a;
    asm("{ .reg .u64 t; cvta.to.shared.u64 t, %1; cvt.u32.u64 %0, t; }" : "=r"(a) : "l"(p));
    return a;
}

#define SWZ(o) ((o) ^ (((o) >> 3) & 0x70))

#define CP_ASYNC16(s, g) \
    asm volatile("cp.async.cg.shared.global [%0], [%1], 16;" :: "r"(s), "l"(g))
#define CP_COMMIT() asm volatile("cp.async.commit_group;")
#define CP_WAIT(n)  asm volatile("cp.async.wait_group %0;" :: "n"(n) : "memory")

#define LDMATRIX_X4(r0, r1, r2, r3, addr)                                     \
    asm volatile("ldmatrix.sync.aligned.m8n8.x4.shared.b16 {%0,%1,%2,%3}, [%4];" \
        : "=r"(r0), "=r"(r1), "=r"(r2), "=r"(r3) : "r"(addr))

#define STS128U(addr, a, b, c, d)                                             \
    asm volatile("st.shared.v4.b32 [%0], {%1,%2,%3,%4};"                      \
        :: "r"(addr), "r"(a), "r"(b), "r"(c), "r"(d))

#define MMA_16816(d, a, b0, b1)                                               \
    asm volatile("mma.sync.aligned.m16n8k16.row.col.f32.f16.f16.f32 "         \
        "{%0,%1,%2,%3}, {%4,%5,%6,%7}, {%8,%9}, {%0,%1,%2,%3};"               \
        : "+f"((d)[0]), "+f"((d)[1]), "+f"((d)[2]), "+f"((d)[3])              \
        : "r"((a)[0]), "r"((a)[1]), "r"((a)[2]), "r"((a)[3]), "r"(b0), "r"(b1))

__device__ __forceinline__ float sgn(float v) {
    return (v > 0.0f) ? 1.0f : ((v < 0.0f) ? -1.0f : 0.0f);
}

__device__ __forceinline__ uint32_t h2u(__half2 h) {
    return *reinterpret_cast<uint32_t*>(&h);
}

// ---------------------------------------------------------------------------
// Prep kernels (B matrices only; x conversion fused into GEMM1)
// ---------------------------------------------------------------------------
__global__ void prep_B1_kernel(const float* __restrict__ V,   const float* __restrict__ VR,
                               const float* __restrict__ v2,  const float* __restrict__ v2R,
                               const float* __restrict__ v1,  const float* __restrict__ v1R,
                               const float* __restrict__ u2,  const float* __restrict__ u2R) {
    int idx = blockIdx.x * blockDim.x + threadIdx.x;   // S_CAT*DIN
    int s = idx >> 12;
    int i = idx & 4095;
    float val;
    if (s < S_RANK) val = sgn(V [(size_t)s * DIN + i]) * v2[i] * v1[s] * u2[s];
    else {
        int s2 = s - S_RANK;
        val = sgn(VR[(size_t)s2 * DIN + i]) * v2R[i] * v1R[s2] * u2R[s2];
    }
    g_B1[idx] = __float2half(val);
}

__global__ void prep_B2_kernel(const float* __restrict__ U,  const float* __restrict__ UR,
                               const float* __restrict__ u1, const float* __restrict__ u1R) {
    int idx = blockIdx.x * blockDim.x + threadIdx.x;   // DOUT*S_CAT
    int j = idx >> 9;
    int s = idx & 511;
    float val;
    if (s < S_RANK) val = sgn(U [(size_t)j * S_RANK + s]) * u1[j];
    else            val = sgn(UR[(size_t)j * S_RANK + (s - S_RANK)]) * u1R[j];
    g_B2[idx] = __float2half(val);
}

// ---------------------------------------------------------------------------
// GEMM1: H[8192,512] = fp16(x[8192,4096]) @ B1[512,4096]^T
// x fp32 -> regs -> fp16 smem, half-split so each LDG has 2-3 ks-blocks of
// MMA cover before its STS. 96KB smem, 2 CTAs/SM.
// ---------------------------------------------------------------------------
__global__ __launch_bounds__(THREADS, 2) void gemm1_kernel(const float* __restrict__ x) {
    extern __shared__ char smem_raw[];
    const uint32_t smA = smem_u32(smem_raw);              // 3 fp16 A stages
    const uint32_t smB = smA + STAGES * TILE_BYTES;       // 3 fp16 B stages
    const int tid  = threadIdx.x;
    const int wid  = tid >> 5;
    const int lane = tid & 31;
    const int m0 = blockIdx.y * BM;
    const int n0 = blockIdx.x * BN;
    constexpr int NIT = DIN / BK;    // 64

    const int wm = wid >> 2;
    const int wn = wid & 3;

    const int ldRow = lane & 15;
    const int ldSel = lane >> 4;
    const uint32_t aOffBase = (uint32_t)((wm * 64 + ldRow) * 128 + ldSel * 16);
    const uint32_t bOffBase = (uint32_t)((wn * 32 + ldRow) * 128 + ldSel * 16);

    // x ownership: thread -> (row, half of the 64-col window). 32 floats/thread,
    // processed as two 16-float halves.
    const int cvRow  = tid >> 1;     // 0..127
    const int cvHalf = tid & 1;      // 0..1
    const float* xrow = x + (size_t)(m0 + cvRow) * DIN + cvHalf * 32;
    const uint32_t stsBase = (uint32_t)(cvRow * 128 + cvHalf * 64);

    float4 xbA[4], xbB[4];           // 16 + 16 floats

    auto ldgH0 = [&](int st) {
        const float4* src = (const float4*)(xrow + (size_t)st * BK);
        #pragma unroll
        for (int i = 0; i < 4; ++i) xbA[i] = src[i];
    };
    auto ldgH1 = [&](int st) {
        const float4* src = (const float4*)(xrow + (size_t)st * BK) + 4;
        #pragma unroll
        for (int i = 0; i < 4; ++i) xbB[i] = src[i];
    };
    auto stsH0 = [&](int st) {
        const uint32_t base = smA + (st % STAGES) * TILE_BYTES;
        #pragma unroll
        for (int j = 0; j < 2; ++j)
            STS128U(base + SWZ(stsBase + (uint32_t)(j * 16)),
                    h2u(__floats2half2_rn(xbA[2*j].x,   xbA[2*j].y)),
                    h2u(__floats2half2_rn(xbA[2*j].z,   xbA[2*j].w)),
                    h2u(__floats2half2_rn(xbA[2*j+1].x, xbA[2*j+1].y)),
                    h2u(__floats2half2_rn(xbA[2*j+1].z, xbA[2*j+1].w)));
    };
    auto stsH1 = [&](int st) {
        const uint32_t base = smA + (st % STAGES) * TILE_BYTES;
        #pragma unroll
        for (int j = 0; j < 2; ++j)
            STS128U(base + SWZ(stsBase + (uint32_t)(32 + j * 16)),
                    h2u(__floats2half2_rn(xbB[2*j].x,   xbB[2*j].y)),
                    h2u(__floats2half2_rn(xbB[2*j].z,   xbB[2*j].w)),
                    h2u(__floats2half2_rn(xbB[2*j+1].x, xbB[2*j+1].y)),
                    h2u(__floats2half2_rn(xbB[2*j+1].z, xbB[2*j+1].w)));
    };
    auto load_B = [&](int st) {
        const uint32_t bb = smB + (st % STAGES) * TILE_BYTES;
        const int k0 = st * BK;
        #pragma unroll
        for (int u = 0; u < 4; ++u) {
            int q = tid + u * THREADS;      // 0..1023
            int row = q >> 3, c = q & 7;
            CP_ASYNC16(bb + SWZ((uint32_t)(row * 128 + c * 16)),
                       g_B1 + (size_t)(n0 + row) * DIN + k0 + c * 8);
        }
    };

    float acc[4][4][4] = {};

    // Prologue: stages 0,1 converted; stage 2's x in flight in regs
    ldgH0(0); ldgH1(0); stsH0(0); stsH1(0);
    ldgH0(1); ldgH1(1); stsH0(1); stsH1(1);
    load_B(0); CP_COMMIT();
    load_B(1); CP_COMMIT();
    ldgH0(2); ldgH1(2);

    #pragma unroll 1
    for (int it = 0; it < NIT; ++it) {
        CP_WAIT(1);
        __syncthreads();    // stage `it` B resident; A STS visible; MMA(it-1) done

        // Stage it+2 ((it+2)%3 == (it-1)%3, freed at the barrier above):
        // STS the x regs loaded during iter it-1, then kick B load.
        if (it + 2 < NIT) { stsH0(it + 2); stsH1(it + 2); load_B(it + 2); }
        CP_COMMIT();

        const uint32_t sA = smA + (it % STAGES) * TILE_BYTES;
        const uint32_t sB = smB + (it % STAGES) * TILE_BYTES;

        #pragma unroll
        for (int ks = 0; ks < 4; ++ks) {
            uint32_t af[4][4], bf[2][4];
            #pragma unroll
            for (int i = 0; i < 4; ++i)
                LDMATRIX_X4(af[i][0], af[i][1], af[i][2], af[i][3],
                            sA + SWZ(aOffBase + (uint32_t)(i * 2048 + ks * 32)));
            #pragma unroll
            for (int jj = 0; jj < 2; ++jj)
                LDMATRIX_X4(bf[jj][0], bf[jj][1], bf[jj][2], bf[jj][3],
                            sB + SWZ(bOffBase + (uint32_t)(jj * 2048 + ks * 32)));
            #pragma unroll
            for (int i = 0; i < 4; ++i)
                #pragma unroll
                for (int j = 0; j < 4; ++j)
                    MMA_16816(acc[i][j], af[i], bf[j >> 1][(j & 1)], bf[j >> 1][(j & 1) + 2]);

            // x prefetch for stage it+3, spread inside the MMA section so each
            // LDG gets 2-3 ks-blocks + barrier of latency cover before its STS.
            if (ks == 0 && it + 3 < NIT) ldgH0(it + 3);
            if (ks == 1 && it + 3 < NIT) ldgH1(it + 3);
        }
    }

    // Epilogue: store H fp16
    const int rBase = m0 + wm * 64 + (lane >> 2);
    const int cBase = n0 + wn * 32 + (lane & 3) * 2;
    #pragma unroll
    for (int i = 0; i < 4; ++i) {
        const int r = rBase + i * 16;
        #pragma unroll
        for (int j = 0; j < 4; ++j) {
            const int c = cBase + j * 8;
            *(__half2*)&g_H[(size_t)r * S_CAT + c] =
                __floats2half2_rn(acc[i][j][0], acc[i][j][1]);
            *(__half2*)&g_H[(size_t)(r + 8) * S_CAT + c] =
                __floats2half2_rn(acc[i][j][2], acc[i][j][3]);
        }
    }
}

// ---------------------------------------------------------------------------
// GEMM2 (measured 106.4us twice): y = H @ B2^T + bias. 128x128, 2 CTAs/SM.
// ---------------------------------------------------------------------------
__global__ __launch_bounds__(THREADS, 2) void gemm2_kernel(float* __restrict__ out,
                                                           const float* __restrict__ bias) {
    extern __shared__ char smem_raw[];
    const uint32_t sm_tiles = smem_u32(smem_raw);
    const int tid  = threadIdx.x;
    const int wid  = tid >> 5;
    const int lane = tid & 31;
    const int m0 = blockIdx.y * BM;
    const int n0 = blockIdx.x * BN;
    constexpr int K   = S_CAT;
    constexpr int NIT = K / BK;      // 8
    constexpr int STAGE2 = 2 * TILE_BYTES;

    const int wm = wid >> 2;
    const int wn = wid & 3;

    const int ldRow = lane & 15;
    const int ldSel = lane >> 4;
    const uint32_t aOffBase = (uint32_t)((wm * 64 + ldRow) * 128 + ldSel * 16);
    const uint32_t bOffBase = (uint32_t)((wn * 32 + ldRow) * 128 + ldSel * 16);

    float acc[4][4][4] = {};

    auto load_stage = [&](int it) {
        const uint32_t sbase = sm_tiles + (it % STAGES) * STAGE2;
        const int k0 = it * BK;
        #pragma unroll
        for (int u = 0; u < 8; ++u) {
            int q = tid + u * THREADS;
            if (q < 1024) {
                int row = q >> 3, c = q & 7;
                CP_ASYNC16(sbase + SWZ((uint32_t)(row * 128 + c * 16)),
                           g_H + (size_t)(m0 + row) * K + k0 + c * 8);
            } else {
                int qb = q - 1024;
                int row = qb >> 3, c = qb & 7;
                CP_ASYNC16(sbase + TILE_BYTES + SWZ((uint32_t)(row * 128 + c * 16)),
                           g_B2 + (size_t)(n0 + row) * K + k0 + c * 8);
            }
        }
    };

    load_stage(0); CP_COMMIT();
    load_stage(1); CP_COMMIT();

    #pragma unroll 1
    for (int it = 0; it < NIT; ++it) {
        CP_WAIT(1);
        __syncthreads();

        if (it + 2 < NIT) load_stage(it + 2);
        CP_COMMIT();

        const uint32_t sA = sm_tiles + (it % STAGES) * STAGE2;
        const uint32_t sB = sA + TILE_BYTES;

        #pragma unroll
        for (int ks = 0; ks < 4; ++ks) {
            uint32_t af[4][4], bf[2][4];
            #pragma unroll
            for (int i = 0; i < 4; ++i)
                LDMATRIX_X4(af[i][0], af[i][1], af[i][2], af[i][3],
                            sA + SWZ(aOffBase + (uint32_t)(i * 2048 + ks * 32)));
            #pragma unroll
            for (int jj = 0; jj < 2; ++jj)
                LDMATRIX_X4(bf[jj][0], bf[jj][1], bf[jj][2], bf[jj][3],
                            sB + SWZ(bOffBase + (uint32_t)(jj * 2048 + ks * 32)));
            #pragma unroll
            for (int i = 0; i < 4; ++i)
                #pragma unroll
                for (int j = 0; j < 4; ++j)
                    MMA_16816(acc[i][j], af[i], bf[j >> 1][(j & 1)], bf[j >> 1][(j & 1) + 2]);
        }
    }

    const int rBase = m0 + wm * 64 + (lane >> 2);
    const int cBase = n0 + wn * 32 + (lane & 3) * 2;
    #pragma unroll
    for (int i = 0; i < 4; ++i) {
        const int r = rBase + i * 16;
        #pragma unroll
        for (int j = 0; j < 4; ++j) {
            const int c = cBase + j * 8;
            const float b0 = bias[c], b1 = bias[c + 1];
            float2 v0 = make_float2(acc[i][j][0] + b0, acc[i][j][1] + b1);
            float2 v1 = make_float2(acc[i][j][2] + b0, acc[i][j][3] + b1);
            *(float2*)&out[(size_t)r * DOUT + c] = v0;
            *(float2*)&out[(size_t)(r + 8) * DOUT + c] = v1;
        }
    }
}

// ---------------------------------------------------------------------------
// Launch
// ---------------------------------------------------------------------------
extern "C" void kernel_launch(void* const* d_in, const int* in_sizes, int n_in,
                              void* d_out, int out_size) {
    const float* x    = (const float*)d_in[0];
    const float* V    = (const float*)d_in[1];
    const float* U    = (const float*)d_in[2];
    const float* v1   = (const float*)d_in[3];
    const float* v2   = (const float*)d_in[4];
    const float* u1   = (const float*)d_in[5];
    const float* u2   = (const float*)d_in[6];
    const float* V_R  = (const float*)d_in[7];
    const float* U_R  = (const float*)d_in[8];
    const float* v1_R = (const float*)d_in[9];
    const float* v2_R = (const float*)d_in[10];
    const float* u1_R = (const float*)d_in[11];
    const float* u2_R = (const float*)d_in[12];
    const float* bias = (const float*)d_in[13];
    float* out = (float*)d_out;

    cudaFuncSetAttribute(gemm1_kernel, cudaFuncAttributeMaxDynamicSharedMemorySize, G_SMEM);
    cudaFuncSetAttribute(gemm2_kernel, cudaFuncAttributeMaxDynamicSharedMemorySize, G_SMEM);

    prep_B1_kernel<<<(S_CAT * DIN) / 256, 256>>>(V, V_R, v2, v2_R, v1, v1_R, u2, u2_R);
    prep_B2_kernel<<<(DOUT * S_CAT) / 256, 256>>>(U, U_R, u1, u1_R);

    // GEMM1: grid (4, 64) = 256 CTAs, 2/SM (x read + converted in-kernel)
    gemm1_kernel<<<dim3(S_CAT / BN, N_TOK / BM), THREADS, G_SMEM>>>(x);

    // GEMM2: grid (32, 64) = 2048 CTAs, 2/SM
    gemm2_kernel<<<dim3(DOUT / BN, N_TOK / BM), THREADS, G_SMEM>>>(out, bias);
}

// round 11
// speedup vs baseline: 1.3675x; 1.3675x over previous
#include <cuda_runtime.h>
#include <cuda_fp16.h>
#include <cstdint>
#include <cstddef>

// ---------------------------------------------------------------------------
// Problem constants
// ---------------------------------------------------------------------------
#define N_TOK   8192
#define DIN     4096
#define DOUT    4096
#define S_RANK  256
#define S_CAT   512

#define BM      128
#define BN      128
#define BK      64          // 64 fp16 = 128B row -> SW128 swizzle
#define STAGES  3
#define THREADS 256

#define TILE_BYTES (128 * 128)                       // 16KB per fp16 tile stage
#define G_SMEM     (STAGES * 2 * TILE_BYTES)         // 98304 -> 2 CTAs/SM

// ---------------------------------------------------------------------------
// Scratch (device globals; no runtime allocation)
// ---------------------------------------------------------------------------
__device__ __half g_xh[(size_t)N_TOK * DIN];     // fp16(x)            64 MB
__device__ __half g_B1[(size_t)S_CAT * DIN];     // sign(V)*v2*v1*u2    4 MB
__device__ __half g_B2[(size_t)DOUT * S_CAT];    // sign(U)*u1          4 MB
__device__ __half g_H [(size_t)N_TOK * S_CAT];   // H fp16              8 MB

// ---------------------------------------------------------------------------
// Helpers
// ---------------------------------------------------------------------------
__device__ __forceinline__ uint32_t smem_u32(const void* p) {
    uint32_t a;
    asm("{ .reg .u64 t; cvta.to.shared.u64 t, %1; cvt.u32.u64 %0, t; }" : "=r"(a) : "l"(p));
    return a;
}

#define SWZ(o) ((o) ^ (((o) >> 3) & 0x70))

#define CP_ASYNC16(s, g) \
    asm volatile("cp.async.cg.shared.global [%0], [%1], 16;" :: "r"(s), "l"(g))
#define CP_COMMIT() asm volatile("cp.async.commit_group;")
#define CP_WAIT(n)  asm volatile("cp.async.wait_group %0;" :: "n"(n) : "memory")

#define LDMATRIX_X4(r0, r1, r2, r3, addr)                                     \
    asm volatile("ldmatrix.sync.aligned.m8n8.x4.shared.b16 {%0,%1,%2,%3}, [%4];" \
        : "=r"(r0), "=r"(r1), "=r"(r2), "=r"(r3) : "r"(addr))

#define MMA_16816(d, a, b0, b1)                                               \
    asm volatile("mma.sync.aligned.m16n8k16.row.col.f32.f16.f16.f32 "         \
        "{%0,%1,%2,%3}, {%4,%5,%6,%7}, {%8,%9}, {%0,%1,%2,%3};"               \
        : "+f"((d)[0]), "+f"((d)[1]), "+f"((d)[2]), "+f"((d)[3])              \
        : "r"((a)[0]), "r"((a)[1]), "r"((a)[2]), "r"((a)[3]), "r"(b0), "r"(b1))

__device__ __forceinline__ float sgn(float v) {
    return (v > 0.0f) ? 1.0f : ((v < 0.0f) ? -1.0f : 0.0f);
}

__device__ __forceinline__ uint32_t h2u(__half2 h) {
    return *reinterpret_cast<uint32_t*>(&h);
}

// ---------------------------------------------------------------------------
// Prep: x -> fp16 (vectorized: 8 floats in, one 16B store out per thread)
// ---------------------------------------------------------------------------
__global__ void prep_x_kernel(const float4* __restrict__ x) {
    size_t i = (size_t)blockIdx.x * blockDim.x + threadIdx.x;   // 4,194,304 threads
    float4 a = x[2 * i];
    float4 b = x[2 * i + 1];
    uint4 o;
    o.x = h2u(__floats2half2_rn(a.x, a.y));
    o.y = h2u(__floats2half2_rn(a.z, a.w));
    o.z = h2u(__floats2half2_rn(b.x, b.y));
    o.w = h2u(__floats2half2_rn(b.z, b.w));
    *reinterpret_cast<uint4*>(&g_xh[8 * i]) = o;
}

// Merged B1+B2 prep: idx < S_CAT*DIN handles B1, rest handles B2.
__global__ void prep_B_kernel(const float* __restrict__ V,   const float* __restrict__ VR,
                              const float* __restrict__ v2,  const float* __restrict__ v2R,
                              const float* __restrict__ v1,  const float* __restrict__ v1R,
                              const float* __restrict__ u2,  const float* __restrict__ u2R,
                              const float* __restrict__ U,   const float* __restrict__ UR,
                              const float* __restrict__ u1,  const float* __restrict__ u1R) {
    int idx = blockIdx.x * blockDim.x + threadIdx.x;
    if (idx < S_CAT * DIN) {                       // B1[s][i]
        int s = idx >> 12;
        int i = idx & 4095;
        float val;
        if (s < S_RANK) val = sgn(V [(size_t)s * DIN + i]) * v2[i] * v1[s] * u2[s];
        else {
            int s2 = s - S_RANK;
            val = sgn(VR[(size_t)s2 * DIN + i]) * v2R[i] * v1R[s2] * u2R[s2];
        }
        g_B1[idx] = __float2half(val);
    } else {                                       // B2[j][s]
        int idx2 = idx - S_CAT * DIN;
        int j = idx2 >> 9;
        int s = idx2 & 511;
        float val;
        if (s < S_RANK) val = sgn(U [(size_t)j * S_RANK + s]) * u1[j];
        else            val = sgn(UR[(size_t)j * S_RANK + (s - S_RANK)]) * u1R[j];
        g_B2[idx2] = __float2half(val);
    }
}

// ---------------------------------------------------------------------------
// HMMA GEMM (R5 champion config): C[M,N] = A[M,K] @ B[N,K]^T, fp16 in, fp32 acc
// CTA 128x128, warps 2x4 of 64x32, 2 CTAs/SM, 3-stage cp.async, prefetch
// before MMA, single barrier pair per iteration.
// EPI==1: store fp16 to g_H.  EPI==2: add bias, store fp32 to out.
// ---------------------------------------------------------------------------
template <int K, int EPI>
__global__ __launch_bounds__(THREADS, 2) void gemm_kernel(float* __restrict__ out,
                                                          const float* __restrict__ bias) {
    extern __shared__ char smem_raw[];
    const uint32_t sm_tiles = smem_u32(smem_raw);
    const int tid  = threadIdx.x;
    const int wid  = tid >> 5;
    const int lane = tid & 31;
    const int m0 = blockIdx.y * BM;
    const int n0 = blockIdx.x * BN;
    constexpr int NIT = K / BK;
    constexpr int STAGE2 = 2 * TILE_BYTES;

    const __half* A = (EPI == 1) ? g_xh : g_H;
    const __half* B = (EPI == 1) ? g_B1 : g_B2;

    const int wm = wid >> 2;
    const int wn = wid & 3;

    const int ldRow = lane & 15;
    const int ldSel = lane >> 4;
    const uint32_t aOffBase = (uint32_t)((wm * 64 + ldRow) * 128 + ldSel * 16);
    const uint32_t bOffBase = (uint32_t)((wn * 32 + ldRow) * 128 + ldSel * 16);

    float acc[4][4][4] = {};   // 64 regs

    auto load_stage = [&](int it) {
        const uint32_t sbase = sm_tiles + (it % STAGES) * STAGE2;
        const int k0 = it * BK;
        #pragma unroll
        for (int u = 0; u < 8; ++u) {
            int q = tid + u * THREADS;            // 0..2047
            if (q < 1024) {                       // A: 128 rows x 8 16B-chunks
                int row = q >> 3, c = q & 7;
                CP_ASYNC16(sbase + SWZ((uint32_t)(row * 128 + c * 16)),
                           A + (size_t)(m0 + row) * K + k0 + c * 8);
            } else {                              // B: 128 rows x 8 chunks
                int qb = q - 1024;
                int row = qb >> 3, c = qb & 7;
                CP_ASYNC16(sbase + TILE_BYTES + SWZ((uint32_t)(row * 128 + c * 16)),
                           B + (size_t)(n0 + row) * K + k0 + c * 8);
            }
        }
    };

    // Prologue
    load_stage(0); CP_COMMIT();
    load_stage(1); CP_COMMIT();

    #pragma unroll 1
    for (int it = 0; it < NIT; ++it) {
        CP_WAIT(1);
        __syncthreads();       // stage `it` resident; MMA(it-1) complete

        // Prefetch stage it+2 into the buffer freed at the barrier above.
        if (it + 2 < NIT) load_stage(it + 2);
        CP_COMMIT();

        const uint32_t sA = sm_tiles + (it % STAGES) * STAGE2;
        const uint32_t sB = sA + TILE_BYTES;

        #pragma unroll
        for (int ks = 0; ks < 4; ++ks) {
            uint32_t af[4][4], bf[2][4];
            #pragma unroll
            for (int i = 0; i < 4; ++i)
                LDMATRIX_X4(af[i][0], af[i][1], af[i][2], af[i][3],
                            sA + SWZ(aOffBase + (uint32_t)(i * 2048 + ks * 32)));
            #pragma unroll
            for (int jj = 0; jj < 2; ++jj)
                LDMATRIX_X4(bf[jj][0], bf[jj][1], bf[jj][2], bf[jj][3],
                            sB + SWZ(bOffBase + (uint32_t)(jj * 2048 + ks * 32)));
            #pragma unroll
            for (int i = 0; i < 4; ++i)
                #pragma unroll
                for (int j = 0; j < 4; ++j)
                    MMA_16816(acc[i][j], af[i], bf[j >> 1][(j & 1)], bf[j >> 1][(j & 1) + 2]);
        }
        __syncthreads();       // all warps done reading stage `it`
    }

    // Epilogue
    const int rBase = m0 + wm * 64 + (lane >> 2);
    const int cBase = n0 + wn * 32 + (lane & 3) * 2;
    #pragma unroll
    for (int i = 0; i < 4; ++i) {
        const int r = rBase + i * 16;
        #pragma unroll
        for (int j = 0; j < 4; ++j) {
            const int c = cBase + j * 8;
            if (EPI == 1) {
                *(__half2*)&g_H[(size_t)r * S_CAT + c] =
                    __floats2half2_rn(acc[i][j][0], acc[i][j][1]);
                *(__half2*)&g_H[(size_t)(r + 8) * S_CAT + c] =
                    __floats2half2_rn(acc[i][j][2], acc[i][j][3]);
            } else {
                const float b0 = bias[c], b1 = bias[c + 1];
                float2 v0 = make_float2(acc[i][j][0] + b0, acc[i][j][1] + b1);
                float2 v1 = make_float2(acc[i][j][2] + b0, acc[i][j][3] + b1);
                *(float2*)&out[(size_t)r * DOUT + c] = v0;
                *(float2*)&out[(size_t)(r + 8) * DOUT + c] = v1;
            }
        }
    }
}

// ---------------------------------------------------------------------------
// Launch
// ---------------------------------------------------------------------------
extern "C" void kernel_launch(void* const* d_in, const int* in_sizes, int n_in,
                              void* d_out, int out_size) {
    const float* x    = (const float*)d_in[0];
    const float* V    = (const float*)d_in[1];
    const float* U    = (const float*)d_in[2];
    const float* v1   = (const float*)d_in[3];
    const float* v2   = (const float*)d_in[4];
    const float* u1   = (const float*)d_in[5];
    const float* u2   = (const float*)d_in[6];
    const float* V_R  = (const float*)d_in[7];
    const float* U_R  = (const float*)d_in[8];
    const float* v1_R = (const float*)d_in[9];
    const float* v2_R = (const float*)d_in[10];
    const float* u1_R = (const float*)d_in[11];
    const float* u2_R = (const float*)d_in[12];
    const float* bias = (const float*)d_in[13];
    float* out = (float*)d_out;

    cudaFuncSetAttribute(gemm_kernel<DIN, 1>,
                         cudaFuncAttributeMaxDynamicSharedMemorySize, G_SMEM);
    cudaFuncSetAttribute(gemm_kernel<S_CAT, 2>,
                         cudaFuncAttributeMaxDynamicSharedMemorySize, G_SMEM);

    // Prep: x conversion (8 floats/thread, 16B stores) + merged B prep
    prep_x_kernel<<<(int)((size_t)N_TOK * DIN / 8 / 256), 256>>>((const float4*)x);
    prep_B_kernel<<<(S_CAT * DIN + DOUT * S_CAT) / 256, 256>>>(
        V, V_R, v2, v2_R, v1, v1_R, u2, u2_R, U, U_R, u1, u1_R);

    // GEMM1: H = fp16(x) @ B1^T   grid (4, 64) = 256 CTAs, 2/SM
    gemm_kernel<DIN, 1><<<dim3(S_CAT / BN, N_TOK / BM), THREADS, G_SMEM>>>(nullptr, nullptr);

    // GEMM2: y = H @ B2^T + bias  grid (32, 64) = 2048 CTAs, 2/SM
    gemm_kernel<S_CAT, 2><<<dim3(DOUT / BN, N_TOK / BM), THREADS, G_SMEM>>>(out, bias);
}